// round 7
// baseline (speedup 1.0000x reference)
#include <cuda_runtime.h>
#include <cuda_fp16.h>
#include <cstdint>
#include <math_constants.h>

// Problem constants
#define DIM      256
#define NPIX     65536      // DIM*DIM
#define NOUT     16384      // HO*HO
#define HALF     32768      // pixels per half-plane
#define TPB      1024
#define OPT      16         // outputs per thread (per plane of the pair)

// L2-resident compressed index table (4 x uint16 per output = 128 KB)
__device__ uint16_t g_idx16[NOUT * 4];

// ---------------------------------------------------------------------------
// Pass 0: compress gather_idx (int64 OR int32, autodetected) -> uint16.
// gather_idx is a permutation of [0,65536): among 8 sampled entries at most
// one is zero, so "first 8 odd u32 words all zero" <=> int64 layout.
// ---------------------------------------------------------------------------
__global__ void cvt_idx_kernel(const uint32_t* __restrict__ src) {
    bool is64 = true;
#pragma unroll
    for (int i = 0; i < 8; i++) is64 &= (src[2 * i + 1] == 0u);
    int t = blockIdx.x * blockDim.x + threadIdx.x;  // 0 .. 65535
    uint32_t v = is64 ? src[2 * t] : src[t];
    g_idx16[t] = (uint16_t)v;
}

// ---------------------------------------------------------------------------
// Main kernel: one CTA per PLANE PAIR (all planes share gather_idx).
// Stage half of both planes interleaved as half2 (128 KB smem): one random
// LDS.32 + hmax2 serves BOTH planes -> random crossbar lanes per plane are
// halved vs R5. Two half-passes; idx quads and half2 accumulators persist in
// registers across passes (idx table read once per pair).
// ---------------------------------------------------------------------------
extern __shared__ __half2 sh2[];   // HALF half2 = 128 KB dynamic

__global__ void __launch_bounds__(TPB, 1)
pool_kernel(const float* __restrict__ x, float* __restrict__ out) {
    const int pair = blockIdx.x;
    const int t = threadIdx.x;

    const float4* __restrict__ xa =
        reinterpret_cast<const float4*>(x + (size_t)(2 * pair) * NPIX);
    const float4* __restrict__ xb =
        reinterpret_cast<const float4*>(x + (size_t)(2 * pair + 1) * NPIX);
    uint4* __restrict__ sh4 = reinterpret_cast<uint4*>(sh2);

    // ---- idx quads for this thread's 16 outputs: read once, keep in regs ----
    const uint2* __restrict__ idx2 = reinterpret_cast<const uint2*>(g_idx16);
    uint2 iq[OPT];
#pragma unroll
    for (int k = 0; k < OPT; k++) iq[k] = __ldg(&idx2[t + k * TPB]);

    __half2 acc[OPT];
    const __half2 ninf = __float2half2_rn(-CUDART_INF_F);
#pragma unroll
    for (int k = 0; k < OPT; k++) acc[k] = ninf;

#pragma unroll
    for (int h = 0; h < 2; h++) {
        const unsigned base = h ? HALF : 0;

        // ---- fill: read half of A and B, interleave as half2, STS.128 ----
#pragma unroll 2
        for (int w = 0; w < 8; w++) {
            const int q = t + w * TPB;              // 0..8191 float4-in-half
            const float4 va = __ldcs(&xa[h * 8192 + q]);
            const float4 vb = __ldcs(&xb[h * 8192 + q]);
            const __half2 p0 = __floats2half2_rn(va.x, vb.x);  // lo=A, hi=B
            const __half2 p1 = __floats2half2_rn(va.y, vb.y);
            const __half2 p2 = __floats2half2_rn(va.z, vb.z);
            const __half2 p3 = __floats2half2_rn(va.w, vb.w);
            uint4 s;
            s.x = *reinterpret_cast<const unsigned*>(&p0);
            s.y = *reinterpret_cast<const unsigned*>(&p1);
            s.z = *reinterpret_cast<const unsigned*>(&p2);
            s.w = *reinterpret_cast<const unsigned*>(&p3);
            sh4[q] = s;                             // sh2[4q .. 4q+3]
        }
        __syncthreads();

        // ---- gather: predicated random LDS.32, one op covers both planes ----
#pragma unroll
        for (int k = 0; k < OPT; k++) {
            unsigned r;
            r = (iq[k].x & 0xFFFFu) - base; if (r < HALF) acc[k] = __hmax2(acc[k], sh2[r]);
            r = (iq[k].x >> 16)     - base; if (r < HALF) acc[k] = __hmax2(acc[k], sh2[r]);
            r = (iq[k].y & 0xFFFFu) - base; if (r < HALF) acc[k] = __hmax2(acc[k], sh2[r]);
            r = (iq[k].y >> 16)     - base; if (r < HALF) acc[k] = __hmax2(acc[k], sh2[r]);
        }
        if (h == 0) __syncthreads();   // protect smem before refill
    }

    // ---- store: unpack half2 accumulators to the two planes (coalesced) ----
    float* __restrict__ oa = out + (size_t)(2 * pair) * NOUT;
    float* __restrict__ ob = oa + NOUT;
#pragma unroll
    for (int k = 0; k < OPT; k++) {
        const int o = t + k * TPB;
        const float2 f = __half22float2(acc[k]);
        oa[o] = f.x;
        ob[o] = f.y;
    }
}

// ---------------------------------------------------------------------------
// Launch
// ---------------------------------------------------------------------------
extern "C" void kernel_launch(void* const* d_in, const int* in_sizes, int n_in,
                              void* d_out, int out_size) {
    const float*    x    = (const float*)d_in[0];
    const uint32_t* gidx = (const uint32_t*)d_in[1];
    float*          out  = (float*)d_out;

    const int planes = in_sizes[0] / NPIX;              // 16*64 = 1024
    const int smem   = HALF * (int)sizeof(__half2);     // 128 KB

    // Immediate (non-stream) API, idempotent -> capture-safe.
    cudaFuncSetAttribute(pool_kernel,
                         cudaFuncAttributeMaxDynamicSharedMemorySize, smem);

    cvt_idx_kernel<<<NPIX / 256, 256>>>(gidx);
    pool_kernel<<<planes / 2, TPB, smem>>>(x, out);
}